// round 16
// baseline (speedup 1.0000x reference)
#include <cuda_runtime.h>
#include <math.h>

#define DD 2048
#define LL 128
#define BB 64
#define NTHR 256
#define WPB (NTHR / 32)          // 8 warps per block -> 8 rows per block
#define NBLK1 (BB * LL / WPB)    // 1024 blocks, one warp per row
#define SPLIT 8                  // pair-space slices per batch
#define NBLK2 (BB * SPLIT)       // 512 blocks in pair kernel
#define TRI   (LL * (LL - 1) / 2)   // 8128 pairs in full triangle

// Scratch (no device allocation allowed)
__device__ float    g_dj[BB * LL];
__device__ float    g_ek[BB * LL];
__device__ float    g_psum[NBLK2];
__device__ float    g_bsum[BB];
__device__ int      g_pcnt[BB];
__device__ unsigned g_sdone[BB];  // per-batch monotonic counters (replay-safe)
__device__ unsigned g_done;       // global monotonic counter

// Fast softplus: MUFU-based. |err| ~1e-6 vs 1e-3 tolerance.
__device__ __forceinline__ float softplus_fast(float x) {
    return fmaxf(x, 0.f) + __logf(1.f + __expf(-fabsf(x)));
}

// ---------------------------------------------------------------------------
// Kernel 1 (UNCHANGED — ~10us, HBM roofline): warp-per-row dual dot products;
// 4 blocks/SM x 8 warps = 32 warps/SM; 8-deep staged __ldcs.
// ---------------------------------------------------------------------------
__global__ __launch_bounds__(NTHR, 4) void rowdot_kernel(
    const float* __restrict__ enc,   // [64,128,2048]
    const float* __restrict__ W)     // [4096,2] row-major
{
    __shared__ float s_wl[DD];
    __shared__ float s_wr[DD];

    const int tid = threadIdx.x;

    for (int d = tid; d < DD; d += NTHR) {
        float2 a = *(const float2*)(W + 2 * d);
        float2 r = *(const float2*)(W + 2 * (DD + d));
        s_wl[d] = a.y - a.x;
        s_wr[d] = r.y - r.x;
    }
    __syncthreads();

    const int warp = tid >> 5;
    const int lane = tid & 31;
    const int row  = blockIdx.x * WPB + warp;
    const float4* e4  = (const float4*)(enc + (size_t)row * DD);
    const float4* wl4 = (const float4*)s_wl;
    const float4* wr4 = (const float4*)s_wr;

    float sd = 0.f, se = 0.f;
#pragma unroll
    for (int half = 0; half < 2; ++half) {
        float4 e[8];
#pragma unroll
        for (int it = 0; it < 8; ++it)
            e[it] = __ldcs(&e4[lane + (half * 8 + it) * 32]);
#pragma unroll
        for (int it = 0; it < 8; ++it) {
            int i = lane + (half * 8 + it) * 32;
            float4 a = wl4[i];
            float4 r = wr4[i];
            sd += e[it].x * a.x + e[it].y * a.y + e[it].z * a.z + e[it].w * a.w;
            se += e[it].x * r.x + e[it].y * r.y + e[it].z * r.z + e[it].w * r.w;
        }
    }
#pragma unroll
    for (int o = 16; o; o >>= 1) {
        sd += __shfl_down_sync(0xFFFFFFFFu, sd, o);
        se += __shfl_down_sync(0xFFFFFFFFu, se, o);
    }
    if (lane == 0) {
        g_dj[row] = sd;
        g_ek[row] = se;
    }
}

// ---------------------------------------------------------------------------
// Kernel 2: 64 batches x 8 slices. Fixed-trip predicated sweep of the full
// 8128-pair triangle; ONE __syncthreads on the critical path; hierarchical
// (per-batch -> global) completion counters to kill atomic contention.
// ---------------------------------------------------------------------------
__global__ __launch_bounds__(NTHR) void pair_kernel(
    const int*   __restrict__ mask,  // [64,128]
    const float* __restrict__ bias,  // [2]
    float* __restrict__ out)
{
    __shared__ float s_dj[LL];
    __shared__ float s_ek[LL];
    __shared__ float s_mred[4];
    __shared__ float s_wred[NTHR / 32];
    __shared__ int   s_blast, s_glast;

    const int blk   = blockIdx.x;
    const int b     = blk >> 3;          // batch
    const int slice = blk & (SPLIT - 1);
    const int tid   = threadIdx.x;
    const int lane  = tid & 31;

    // Overlapped loads: mask warp-reduce partials + dj/ek smem fill, ONE sync.
    if (tid < LL) {
        int v = mask[b * LL + tid];
#pragma unroll
        for (int o = 16; o; o >>= 1)
            v += __shfl_down_sync(0xFFFFFFFFu, v, o);
        if (lane == 0) s_mred[tid >> 5] = (float)v;
        s_dj[tid] = __ldcg(&g_dj[b * LL + tid]);
        s_ek[tid] = __ldcg(&g_ek[b * LL + tid]);
    }
    __syncthreads();

    const int   len = (int)(s_mred[0] + s_mred[1] + s_mred[2] + s_mred[3] + 0.5f);
    const float db  = bias[1] - bias[0];

    // Fixed-trip loop over the full triangle, predicated on j < len.
    float acc = 0.f;
#pragma unroll
    for (int s = 0; s < TRI / (NTHR * SPLIT) + 1; ++s) {   // 4 iterations
        int idx = slice * NTHR + tid + s * (NTHR * SPLIT);
        if (idx < TRI) {
            int j = (int)((1.0f + sqrtf(1.0f + 8.0f * (float)idx)) * 0.5f);
            while (j * (j - 1) / 2 > idx) --j;
            while ((j + 1) * j / 2 <= idx) ++j;
            int k = idx - j * (j - 1) / 2;
            float x = s_dj[j] + s_ek[k] + db;
            if (k == j - 1) x = -x;          // label 1 -> softplus(-(z1-z0))
            if (j < len) acc += softplus_fast(x);
        }
    }

    // Block reduce: warp shuffles -> 8 partials -> thread 0.
#pragma unroll
    for (int o = 16; o; o >>= 1)
        acc += __shfl_down_sync(0xFFFFFFFFu, acc, o);
    if (lane == 0) s_wred[tid >> 5] = acc;
    __syncthreads();
    if (tid == 0) {
        float v = 0.f;
#pragma unroll
        for (int w = 0; w < NTHR / 32; ++w) v += s_wred[w];
        __stcg(&g_psum[blk], v);
        __threadfence();
        unsigned o1 = atomicAdd(&g_sdone[b], 1u);     // per-batch: no contention
        s_blast = ((o1 % (unsigned)SPLIT) == (unsigned)(SPLIT - 1));
        s_glast = 0;
    }
    __syncthreads();

    if (s_blast) {
        if (tid == 0) {
            __threadfence();
            float s = 0.f;
#pragma unroll
            for (int i = 0; i < SPLIT; ++i) s += __ldcg(&g_psum[b * SPLIT + i]);
            __stcg(&g_bsum[b], s);
            __stcg(&g_pcnt[b], len * (len - 1) / 2);
            __threadfence();
            unsigned o2 = atomicAdd(&g_done, 1u);     // only 64 ops, spread
            s_glast = ((o2 % (unsigned)BB) == (unsigned)(BB - 1));
        }
        __syncthreads();

        if (s_glast) {
            __threadfence();
            float v = (tid < BB) ? __ldcg(&g_bsum[tid]) : 0.f;
            int   c = (tid < BB) ? __ldcg(&g_pcnt[tid]) : 0;
#pragma unroll
            for (int o = 16; o; o >>= 1) {
                v += __shfl_down_sync(0xFFFFFFFFu, v, o);
                c += __shfl_down_sync(0xFFFFFFFFu, c, o);
            }
            if (tid < BB && lane == 0) {
                s_wred[tid >> 5] = v;
                s_mred[tid >> 5] = (float)c;
            }
            __syncthreads();
            if (tid == 0) {
                float sum = s_wred[0] + s_wred[1];
                int   cnt = (int)(s_mred[0] + s_mred[1] + 0.5f);
                if (cnt < 1) cnt = 1;
                out[0] = sum / (float)cnt;
            }
        }
    }
}

extern "C" void kernel_launch(void* const* d_in, const int* in_sizes, int n_in,
                              void* d_out, int out_size) {
    const float* enc  = (const float*)d_in[0];  // [64,128,2048] f32
    const int*   mask = (const int*)d_in[1];    // [64,128] i32
    const float* W    = (const float*)d_in[2];  // [4096,2] f32
    const float* bias = (const float*)d_in[3];  // [2] f32
    float* out = (float*)d_out;

    rowdot_kernel<<<NBLK1, NTHR>>>(enc, W);
    pair_kernel<<<NBLK2, NTHR>>>(mask, bias, out);
}